// round 15
// baseline (speedup 1.0000x reference)
#include <cuda_runtime.h>
#include <math.h>
#include <stdint.h>

#define NLY 6
#define DM 256
#define FFD 1024
#define VC 1024
#define SL 48
#define BSZ 64
#define NH 8
#define DHD 32
#define LT 49
#define ROWS_E (BSZ*SL)
#define NB 148
#define NT 512

// ---------------- device scratch ----------------
__device__ __align__(16) float g_pe[LT*DM];
__device__ unsigned g_keys[2*SL];
__device__ __align__(16) float g_X[ROWS_E*DM];
__device__ __align__(16) float g_T1[ROWS_E*FFD];
__device__ __align__(16) float g_T2[ROWS_E*DM];
__device__ __align__(16) float g_T3[ROWS_E*DM];
__device__ __align__(16) float g_mem[ROWS_E*DM];
__device__ __align__(16) float g_cK[NLY*ROWS_E*DM];
__device__ __align__(16) float g_cV[NLY*ROWS_E*DM];
__device__ __align__(16) float g_sK[NLY*BSZ*LT*DM];
__device__ __align__(16) float g_sV[NLY*BSZ*LT*DM];
__device__ unsigned g_barcnt = 0;
__device__ unsigned g_bargen = 0;

struct Prm {
  const int *xc, *xcat;
  const float *sos, *emb, *hw, *hb;
  const float *ewqkv, *ebqkv, *ewo, *ebo, *ew1, *eb1, *ew2, *eb2, *elnw, *elnb;
  const float *swqkv, *sbqkv, *swo, *sbo;
  const float *cwqkv, *cbqkv, *cwo, *cbo;
  const float *dw1, *db1, *dw2, *db2, *dlnw, *dlnb, *lnfw, *lnfb;
  float* out;
};

// ---------------- grid barrier (encoder phases only) ----------------
__device__ __forceinline__ void gridbar() {
  __threadfence();
  __syncthreads();
  if (threadIdx.x == 0) {
    unsigned gen = *(volatile unsigned*)&g_bargen;
    if (atomicAdd(&g_barcnt, 1u) == NB - 1u) {
      g_barcnt = 0u;
      __threadfence();
      atomicAdd(&g_bargen, 1u);
    } else {
      while (*(volatile unsigned*)&g_bargen == gen) __nanosleep(64);
    }
  }
  __syncthreads();
  __threadfence();   // gpu-scope => invalidate stale L1 lines
}

// ---------------- Threefry-2x32, 20 rounds ----------------
__device__ __forceinline__ uint2 tf2x32(unsigned k0, unsigned k1,
                                        unsigned x0, unsigned x1) {
  unsigned ks2 = k0 ^ k1 ^ 0x1BD11BDAu;
  x0 += k0; x1 += k1;
#define TFR(r) { x0 += x1; x1 = (x1 << (r)) | (x1 >> (32 - (r))); x1 ^= x0; }
  TFR(13) TFR(15) TFR(26) TFR(6)   x0 += k1;  x1 += ks2 + 1u;
  TFR(17) TFR(29) TFR(16) TFR(24)  x0 += ks2; x1 += k0 + 2u;
  TFR(13) TFR(15) TFR(26) TFR(6)   x0 += k0;  x1 += k1 + 3u;
  TFR(17) TFR(29) TFR(16) TFR(24)  x0 += k1;  x1 += ks2 + 4u;
  TFR(13) TFR(15) TFR(26) TFR(6)   x0 += ks2; x1 += k0 + 5u;
#undef TFR
  return make_uint2(x0, x1);
}

__device__ __forceinline__ float pef(int l, int d) {
  const float c = (float)(-9.210340371976184 / 256.0);
  float dv = expf((float)(2 * (d >> 1)) * c);
  float ang = (float)l * dv;
  return (d & 1) ? cosf(ang) : sinf(ang);
}

// dual-row dot: one weight stream (n4 float4), two x vectors (smem)
__device__ __forceinline__ void dotn2(const float* xa_, const float* xb_,
                                      const float* w_, int n4,
                                      float& oa, float& ob) {
  float a0 = 0.f, a1 = 0.f, b0 = 0.f, b1 = 0.f;
  const float4* xa = (const float4*)xa_;
  const float4* xb = (const float4*)xb_;
  const float4* w4 = (const float4*)w_;
#pragma unroll 4
  for (int i = 0; i < n4; i += 2) {
    float4 wA = __ldg(w4 + i), wB = __ldg(w4 + i + 1);
    float4 u0 = xa[i], u1 = xa[i + 1], v0 = xb[i], v1 = xb[i + 1];
    a0 = fmaf(u0.x,wA.x,fmaf(u0.y,wA.y,fmaf(u0.z,wA.z,fmaf(u0.w,wA.w,a0))));
    a1 = fmaf(u1.x,wB.x,fmaf(u1.y,wB.y,fmaf(u1.z,wB.z,fmaf(u1.w,wB.w,a1))));
    b0 = fmaf(v0.x,wA.x,fmaf(v0.y,wA.y,fmaf(v0.z,wA.z,fmaf(v0.w,wA.w,b0))));
    b1 = fmaf(v1.x,wB.x,fmaf(v1.y,wB.y,fmaf(v1.z,wB.z,fmaf(v1.w,wB.w,b1))));
  }
  oa = a0 + a1; ob = b0 + b1;
}

// 32-float dot (smem q x global k-row)
__device__ __forceinline__ float dot32(const float* q, const float* k) {
  float s = 0.f;
  const float4* a = (const float4*)q;
  const float4* b = (const float4*)k;
#pragma unroll
  for (int i = 0; i < 8; i++) {
    float4 x = a[i], y = __ldg(b + i);
    s = fmaf(x.x,y.x,fmaf(x.y,y.y,fmaf(x.z,y.z,fmaf(x.w,y.w,s))));
  }
  return s;
}

// full-block sum over 512 threads (inactive contribute 0)
__device__ __forceinline__ float blksumall(float v, float* red) {
  int lane = threadIdx.x & 31, wp = threadIdx.x >> 5;
#pragma unroll
  for (int o = 16; o; o >>= 1) v += __shfl_xor_sync(0xffffffffu, v, o);
  if (!lane) red[wp] = v;
  __syncthreads();
  float t = 0.f;
#pragma unroll
  for (int i = 0; i < 16; i++) t += red[i];
  __syncthreads();
  return t;
}

// row-split sum: warps 0-7 = row A, warps 8-15 = row B
__device__ __forceinline__ float blksumrow(float v, float* red) {
  int lane = threadIdx.x & 31, wp = threadIdx.x >> 5;
#pragma unroll
  for (int o = 16; o; o >>= 1) v += __shfl_xor_sync(0xffffffffu, v, o);
  if (!lane) red[wp] = v;
  __syncthreads();
  int base = (threadIdx.x >= 256) ? 8 : 0;
  float t = 0.f;
#pragma unroll
  for (int i = 0; i < 8; i++) t += red[base + i];
  __syncthreads();
  return t;
}

// per-row LayerNorm value (row-split across thread halves)
__device__ __forceinline__ float ln2(float val, const float* w, const float* b,
                                     float* red, int n) {
  float mean = blksumrow(val, red) * (1.f / 256.f);
  float dd = val - mean;
  float var = blksumrow(dd * dd, red) * (1.f / 256.f);
  return dd * rsqrtf(var + 1e-5f) * __ldg(w + n) + __ldg(b + n);
}

// 64x64 tile of C = A(M,K)@B(N,K)^T + bias (+resid)(+relu); 512 threads
__device__ __noinline__ void gtile(const float* A, const float* B,
                                   const float* bias, const float* resid,
                                   float* C, int N, int K, int relu,
                                   int bx, int by, float* SM) {
  float* As = SM;              // [32][68]
  float* Bs = SM + 32 * 68;    // [32][68]
  int t = threadIdx.x, tx = t & 15, ty = t >> 4;
  float acc[2][4] = {};
  const float* Ab = A + (size_t)(by * 64) * K;
  const float* Bb = B + (size_t)(bx * 64) * K;
  int lrow = t >> 3, lcol = (t & 7) * 4;
  for (int k0 = 0; k0 < K; k0 += 32) {
    float4 va = *(const float4*)(Ab + (size_t)lrow * K + k0 + lcol);
    As[(lcol + 0) * 68 + lrow] = va.x; As[(lcol + 1) * 68 + lrow] = va.y;
    As[(lcol + 2) * 68 + lrow] = va.z; As[(lcol + 3) * 68 + lrow] = va.w;
    float4 vb = *(const float4*)(Bb + (size_t)lrow * K + k0 + lcol);
    Bs[(lcol + 0) * 68 + lrow] = vb.x; Bs[(lcol + 1) * 68 + lrow] = vb.y;
    Bs[(lcol + 2) * 68 + lrow] = vb.z; Bs[(lcol + 3) * 68 + lrow] = vb.w;
    __syncthreads();
#pragma unroll
    for (int kk = 0; kk < 32; kk++) {
      float a[2], bb[4];
#pragma unroll
      for (int i = 0; i < 2; i++) a[i] = As[kk * 68 + ty * 2 + i];
#pragma unroll
      for (int j = 0; j < 4; j++) bb[j] = Bs[kk * 68 + tx * 4 + j];
#pragma unroll
      for (int i = 0; i < 2; i++)
#pragma unroll
        for (int j = 0; j < 4; j++) acc[i][j] = fmaf(a[i], bb[j], acc[i][j]);
    }
    __syncthreads();
  }
#pragma unroll
  for (int i = 0; i < 2; i++) {
    int m = by * 64 + ty * 2 + i;
#pragma unroll
    for (int j = 0; j < 4; j++) {
      int n = bx * 64 + tx * 4 + j;
      float v = acc[i][j];
      if (bias)  v += __ldg(bias + n);
      if (resid) v += resid[(size_t)m * N + n];
      if (relu)  v = fmaxf(v, 0.f);
      C[(size_t)m * N + n] = v;
    }
  }
  __syncthreads();
}

// encoder self-attn for one (head, batch); 512 threads / 16 warps
__device__ __noinline__ void enc_attn_unit(const float* QKV, float* O,
                                           int h, int b, float* SM) {
  float* Qs = SM;
  float* Ks = SM + 1536;
  float* Vs = SM + 3072;
  float* pr = SM + 4608;     // [16][48]
  int t = threadIdx.x;
  for (int e = t; e < SL * DHD; e += NT) {
    int j = e >> 5, d = e & 31;
    const float* base = QKV + (size_t)(b * SL + j) * 768 + h * DHD + d;
    Qs[e] = base[0]; Ks[e] = base[256]; Vs[e] = base[512];
  }
  __syncthreads();
  int w = t >> 5, lane = t & 31;
  const float scale = 0.17677669529663687f;
  for (int q = w; q < SL; q += 16) {
    float s0 = 0.f, s1 = -1e30f;
#pragma unroll
    for (int d = 0; d < DHD; d++) s0 += Qs[q * 32 + d] * Ks[lane * 32 + d];
    s0 *= scale;
    if (lane < SL - 32) {
      float a = 0.f;
#pragma unroll
      for (int d = 0; d < DHD; d++) a += Qs[q * 32 + d] * Ks[(lane + 32) * 32 + d];
      s1 = a * scale;
    }
    float mx = fmaxf(s0, s1);
#pragma unroll
    for (int o = 16; o; o >>= 1) mx = fmaxf(mx, __shfl_xor_sync(~0u, mx, o));
    float e0 = expf(s0 - mx);
    float e1 = (lane < SL - 32) ? expf(s1 - mx) : 0.f;
    float sum = e0 + e1;
#pragma unroll
    for (int o = 16; o; o >>= 1) sum += __shfl_xor_sync(~0u, sum, o);
    float inv = 1.f / sum;
    pr[w * SL + lane] = e0 * inv;
    if (lane < SL - 32) pr[w * SL + lane + 32] = e1 * inv;
    __syncwarp();
    float acc = 0.f;
#pragma unroll 8
    for (int j = 0; j < SL; j++) acc += pr[w * SL + j] * Vs[j * 32 + lane];
    O[(size_t)(b * SL + q) * DM + h * DHD + lane] = acc;
    __syncwarp();
  }
  __syncthreads();
}

__device__ __forceinline__ void ln_rows(const float* x, const float* w,
                                        const float* b, float* out, int M,
                                        float* red) {
  int t = threadIdx.x;
  for (int r = blockIdx.x; r < M; r += NB) {
    float v = (t < 256) ? x[(size_t)r * DM + t] : 0.f;
    float mean = blksumall(v, red) * (1.f / 256.f);
    float dd = v - mean;
    float var = blksumall((t < 256) ? dd * dd : 0.f, red) * (1.f / 256.f);
    if (t < 256)
      out[(size_t)r * DM + t] = dd * rsqrtf(var + 1e-5f) * w[t] + b[t];
  }
}

// ---------------- the megakernel ----------------
__global__ __launch_bounds__(NT, 1) void mega(Prm p) {
  __shared__ __align__(16) float SM[6144];
  const int bid = blockIdx.x, tid = threadIdx.x;
  const int gtid = bid * NT + tid;
  const int GT = NB * NT;
  const float scale = 0.17677669529663687f;

  // ---- init: pe, step keys, encoder embed ----
  for (int e = gtid; e < LT * DM; e += GT) g_pe[e] = pef(e >> 8, e & 255);
  if (gtid < SL) {
    uint2 r = tf2x32(0u, 42u, 0u, (unsigned)gtid);
    g_keys[2 * gtid] = r.x; g_keys[2 * gtid + 1] = r.y;
  }
  for (int e = gtid; e < ROWS_E * DM; e += GT) {
    int r = e >> 8, d = e & 255, b = r / SL, s = r % SL;
    int tok = (s < 32) ? p.xc[b * 32 + s] : p.xcat[b * 16 + (s - 32)];
    g_X[e] = p.emb[((size_t)s * VC + tok) * DM + d] + pef(s, d);
  }
  gridbar();

  // ---- encoder ----
  for (int l = 0; l < NLY; l++) {
    for (int t = bid; t < 576; t += NB)
      gtile(g_X, p.ewqkv + (size_t)l * 196608, p.ebqkv + l * 768, nullptr,
            g_T1, 768, 256, 0, t % 12, t / 12, SM);
    gridbar();
    for (int u = bid; u < NH * BSZ; u += NB)
      enc_attn_unit(g_T1, g_T2, u & 7, u >> 3, SM);
    gridbar();
    for (int t = bid; t < 192; t += NB)
      gtile(g_T2, p.ewo + (size_t)l * 65536, p.ebo + l * 256, g_X,
            g_T3, 256, 256, 0, t % 4, t / 4, SM);
    gridbar();
    ln_rows(g_T3, p.elnw + l * 512, p.elnb + l * 512, g_X, ROWS_E, SM);
    gridbar();
    for (int t = bid; t < 768; t += NB)
      gtile(g_X, p.ew1 + (size_t)l * 262144, p.eb1 + l * 1024, nullptr,
            g_T1, 1024, 256, 1, t % 16, t / 16, SM);
    gridbar();
    for (int t = bid; t < 192; t += NB)
      gtile(g_T1, p.ew2 + (size_t)l * 262144, p.eb2 + l * 256, g_X,
            g_T2, 256, 1024, 0, t % 4, t / 4, SM);
    gridbar();
    ln_rows(g_T2, p.elnw + l * 512 + 256, p.elnb + l * 512 + 256, g_X, ROWS_E, SM);
    gridbar();
  }
  ln_rows(g_X, p.lnfw, p.lnfb, g_mem, ROWS_E, SM);
  gridbar();

  // ---- cross-attn K/V precompute ----
  for (int t = bid; t < 2304; t += NB) {
    int l = t / 384, r = t % 384, kv = r / 192, tile = r % 192;
    const float* B = p.cwqkv + (size_t)l * 196608 + (size_t)(256 + kv * 256) * 256;
    const float* bias = p.cbqkv + l * 768 + 256 + kv * 256;
    float* C = (kv ? g_cV : g_cK) + (size_t)l * ROWS_E * DM;
    gtile(g_mem, B, bias, nullptr, C, 256, 256, 0, tile % 4, tile / 4, SM);
  }
  gridbar();   // last grid barrier

  if (bid >= 32) return;   // 32 blocks decode, 2 batch rows each

  // ---- decode: rows bA, bB per block; warps 0-7 <-> row A, 8-15 <-> row B
  const int bA = 2 * bid, bB = bA + 1;
  float* xA  = SM;        float* xB  = SM + 256;
  float* qA  = SM + 512;  float* qB  = SM + 768;
  float* oA  = SM + 1024; float* oB  = SM + 1280;
  float* prA = SM + 1536; float* prB = SM + 1936;
  float* red = SM + 2336;
  float* hbA = SM + 2560; float* hbB = SM + 3584;
  float* bv  = SM + 4608;
  int*   bix = (int*)(SM + 5120);
  int*   chs = (int*)(SM + 5632);   // chsA[48] then chsB[48]
  const int w = tid >> 5, lane = tid & 31;
  const int half = tid >> 8;
  const int nn = tid & 255;

  if (tid < 256) xA[nn] = p.sos[nn] + g_pe[nn];
  else           xB[nn] = p.sos[nn] + g_pe[nn];
  __syncthreads();

  for (int step = 0; step < SL; step++) {
    for (int l = 0; l < NLY; l++) {
      float* KcA = g_sK + (size_t)(l * BSZ + bA) * LT * DM;
      float* KcB = g_sK + (size_t)(l * BSZ + bB) * LT * DM;
      float* VcA = g_sV + (size_t)(l * BSZ + bA) * LT * DM;
      float* VcB = g_sV + (size_t)(l * BSZ + bB) * LT * DM;
      // --- qkv GEMV: 768 outputs x 2 rows, weight rows read once ---
      {
        const float* W = p.swqkv + (size_t)l * 196608;
        const float* bias = p.sbqkv + l * 768;
        {
          int n = tid; float ya, yb;
          dotn2(xA, xB, W + (size_t)n * 256, 64, ya, yb);
          float bs = __ldg(bias + n);
          ya += bs; yb += bs;
          if (n < 256) { qA[n] = ya; qB[n] = yb; }
          else { KcA[step * DM + n - 256] = ya; KcB[step * DM + n - 256] = yb; }
        }
        if (tid < 256) {
          int n = 512 + tid; float ya, yb;
          dotn2(xA, xB, W + (size_t)n * 256, 64, ya, yb);
          float bs = __ldg(bias + n);
          VcA[step * DM + tid] = ya + bs;
          VcB[step * DM + tid] = yb + bs;
        }
        __syncthreads();
      }
      // --- self-attention: 16 warp units (2 rows x 8 heads) ---
      {
        int rw = w >> 3, h = w & 7;
        const float* qq = rw ? qB : qA;
        const float* Kb = (rw ? KcB : KcA) + h * DHD;
        const float* Vb = (rw ? VcB : VcA) + h * DHD;
        float* prr = rw ? prB : prA;
        float* oo  = rw ? oB : oA;
        float s0 = -1e30f, s1 = -1e30f;
        if (lane <= step)      s0 = dot32(qq + h * 32, Kb + lane * DM) * scale;
        if (lane + 32 <= step) s1 = dot32(qq + h * 32, Kb + (lane + 32) * DM) * scale;
        float mx = fmaxf(s0, s1);
#pragma unroll
        for (int o = 16; o; o >>= 1) mx = fmaxf(mx, __shfl_xor_sync(~0u, mx, o));
        float e0 = (lane <= step) ? expf(s0 - mx) : 0.f;
        float e1 = (lane + 32 <= step) ? expf(s1 - mx) : 0.f;
        float sum = e0 + e1;
#pragma unroll
        for (int o = 16; o; o >>= 1) sum += __shfl_xor_sync(~0u, sum, o);
        float inv = 1.f / sum;
        prr[h * LT + lane] = e0 * inv;
        if (lane + 32 < LT) prr[h * LT + lane + 32] = e1 * inv;
        __syncwarp();
        float acc = 0.f;
#pragma unroll 4
        for (int j = 0; j <= step; j++) acc += prr[h * LT + j] * Vb[j * DM + lane];
        oo[h * 32 + lane] = acc;
        __syncthreads();
      }
      // --- self out-proj (K-split) + resid + LN ---
      {
        const float* W = p.swo + (size_t)l * 65536;
        float pa, pb;
        dotn2(oA + half * 128, oB + half * 128,
              W + (size_t)nn * 256 + half * 128, 32, pa, pb);
        hbA[tid] = pa; hbB[tid] = pb;
        __syncthreads();
        float resid = (tid < 256) ? xA[nn] : xB[nn];
        float val = resid + __ldg(p.sbo + l * 256 + nn) +
                    ((tid < 256) ? hbA[nn] + hbA[nn + 256]
                                 : hbB[nn] + hbB[nn + 256]);
        float y = ln2(val, p.dlnw + l * 768, p.dlnb + l * 768, red, nn);
        if (tid < 256) xA[nn] = y; else xB[nn] = y;
        __syncthreads();
      }
      // --- cross Q GEMV (K-split) ---
      {
        const float* W = p.cwqkv + (size_t)l * 196608;
        float pa, pb;
        dotn2(xA + half * 128, xB + half * 128,
              W + (size_t)nn * 256 + half * 128, 32, pa, pb);
        hbA[tid] = pa; hbB[tid] = pb;
        __syncthreads();
        float bs = __ldg(p.cbqkv + l * 768 + nn);
        if (tid < 256) qA[nn] = bs + hbA[nn] + hbA[nn + 256];
        else           qB[nn] = bs + hbB[nn] + hbB[nn + 256];
        __syncthreads();
      }
      // --- cross-attention: 16 warp units over cached memory K/V ---
      {
        int rw = w >> 3, h = w & 7;
        int bb = rw ? bB : bA;
        const float* qq = rw ? qB : qA;
        const float* Kb = g_cK + ((size_t)l * ROWS_E + bb * SL) * DM + h * DHD;
        const float* Vb = g_cV + ((size_t)l * ROWS_E + bb * SL) * DM + h * DHD;
        float* prr = rw ? prB : prA;
        float* oo  = rw ? oB : oA;
        float s0 = dot32(qq + h * 32, Kb + lane * DM) * scale;
        float s1 = (lane < SL - 32)
                   ? dot32(qq + h * 32, Kb + (lane + 32) * DM) * scale : -1e30f;
        float mx = fmaxf(s0, s1);
#pragma unroll
        for (int o = 16; o; o >>= 1) mx = fmaxf(mx, __shfl_xor_sync(~0u, mx, o));
        float e0 = expf(s0 - mx);
        float e1 = (lane < SL - 32) ? expf(s1 - mx) : 0.f;
        float sum = e0 + e1;
#pragma unroll
        for (int o = 16; o; o >>= 1) sum += __shfl_xor_sync(~0u, sum, o);
        float inv = 1.f / sum;
        prr[h * SL + lane] = e0 * inv;
        if (lane < SL - 32) prr[h * SL + lane + 32] = e1 * inv;
        __syncwarp();
        float acc = 0.f;
#pragma unroll 8
        for (int j = 0; j < SL; j++) acc += prr[h * SL + j] * Vb[j * DM + lane];
        oo[h * 32 + lane] = acc;
        __syncthreads();
      }
      // --- cross out-proj (K-split) + resid + LN ---
      {
        const float* W = p.cwo + (size_t)l * 65536;
        float pa, pb;
        dotn2(oA + half * 128, oB + half * 128,
              W + (size_t)nn * 256 + half * 128, 32, pa, pb);
        hbA[tid] = pa; hbB[tid] = pb;
        __syncthreads();
        float resid = (tid < 256) ? xA[nn] : xB[nn];
        float val = resid + __ldg(p.cbo + l * 256 + nn) +
                    ((tid < 256) ? hbA[nn] + hbA[nn + 256]
                                 : hbB[nn] + hbB[nn + 256]);
        float y = ln2(val, p.dlnw + l * 768 + 256, p.dlnb + l * 768 + 256, red, nn);
        if (tid < 256) xA[nn] = y; else xB[nn] = y;
        __syncthreads();
      }
      // --- FF1: 1024 outputs x 2 rows, relu ---
      {
        const float* W1 = p.dw1 + (size_t)l * 262144;
#pragma unroll
        for (int j = 0; j < 2; j++) {
          int n = tid + j * 512;
          float ya, yb;
          dotn2(xA, xB, W1 + (size_t)n * 256, 64, ya, yb);
          float bs = __ldg(p.db1 + l * 1024 + n);
          hbA[n] = fmaxf(ya + bs, 0.f);
          hbB[n] = fmaxf(yb + bs, 0.f);
        }
        __syncthreads();
      }
      // --- FF2 (K-split over 1024) + resid + LN ---
      {
        const float* W2 = p.dw2 + (size_t)l * 262144;
        float pa, pb;
        dotn2(hbA + half * 512, hbB + half * 512,
              W2 + (size_t)nn * 1024 + half * 512, 128, pa, pb);
        bv[tid] = pa; oA[tid] = pb;
        __syncthreads();
        float resid = (tid < 256) ? xA[nn] : xB[nn];
        float val = resid + __ldg(p.db2 + l * 256 + nn) +
                    ((tid < 256) ? bv[nn] + bv[nn + 256]
                                 : oA[nn] + oA[nn + 256]);
        float y = ln2(val, p.dlnw + l * 768 + 512, p.dlnb + l * 768 + 512, red, nn);
        if (tid < 256) xA[nn] = y; else xB[nn] = y;
        __syncthreads();
      }
    }
    // --- final LN ---
    {
      float v = (tid < 256) ? xA[nn] : xB[nn];
      float y = ln2(v, p.lnfw + 256, p.lnfb + 256, red, nn);
      if (tid < 256) qA[nn] = y; else qB[nn] = y;
      __syncthreads();
    }
    // --- head GEMV + logits out + Gumbel-max sample + next-token embed ---
    {
      const float* HW = p.hw + (size_t)step * VC * DM;
      const float* HB = p.hb + step * VC;
      float* outA = p.out + 3072 + ((size_t)step * BSZ + bA) * VC;
      float* outB = outA + VC;
#pragma unroll
      for (int j = 0; j < 2; j++) {
        int n = tid + j * 512;
        float ya, yb;
        dotn2(qA, qB, HW + (size_t)n * 256, 64, ya, yb);
        float bs = __ldg(HB + n);
        ya += bs; yb += bs;
        hbA[n] = ya; hbB[n] = yb;
        outA[n] = ya; outB[n] = yb;
      }
      __syncthreads();
      unsigned k0 = g_keys[2 * step], k1 = g_keys[2 * step + 1];
      const float tiny = 1.17549435e-38f;
      int bglob = (tid < 256) ? bA : bB;
      const float* lgs = (tid < 256) ? hbA : hbB;
      float best = -1e38f; int bi = 0;
#pragma unroll
      for (int j = 0; j < 4; j++) {
        int v = nn + 256 * j;
        uint2 r = tf2x32(k0, k1, 0u, (unsigned)(bglob * VC + v));
        unsigned bits = r.x ^ r.y;
        float f = __uint_as_float((bits >> 9) | 0x3f800000u) - 1.0f;
        float u = fmaxf(tiny, f + tiny);
        float g = -logf(-logf(u));
        float vv = g + __fdiv_rn(lgs[v], 0.1f);
        if (vv > best) { best = vv; bi = v; }
      }
      bv[tid] = best; bix[tid] = bi;
      __syncthreads();
      for (int off = 128; off; off >>= 1) {
        if ((tid & 255) < off) {
          float ov = bv[tid + off]; int oi = bix[tid + off];
          if (ov > bv[tid] || (ov == bv[tid] && oi < bix[tid])) {
            bv[tid] = ov; bix[tid] = oi;
          }
        }
        __syncthreads();
      }
      if (tid == 0)   chs[step] = bix[0];
      if (tid == 256) chs[48 + step] = bix[256];
      if (step < SL - 1) {
        int ch = (tid < 256) ? bix[0] : bix[256];
        float e = __ldg(p.emb + ((size_t)step * VC + ch) * DM + nn) +
                  g_pe[(step + 1) * DM + nn];
        if (tid < 256) xA[nn] = e; else xB[nn] = e;
      }
      __syncthreads();
    }
  }
  // ---- outputs: s_cont [64,32] then s_cat [64,16] ----
  if (tid < 32)                        p.out[bA * 32 + tid] = (float)chs[tid];
  else if (tid < 48)                   p.out[2048 + bA * 16 + (tid - 32)] = (float)chs[tid];
  else if (tid >= 256 && tid < 288)    p.out[bB * 32 + (tid - 256)] = (float)chs[48 + tid - 256];
  else if (tid >= 288 && tid < 304)    p.out[2048 + bB * 16 + (tid - 288)] = (float)chs[80 + (tid - 288)];
}

extern "C" void kernel_launch(void* const* d_in, const int* in_sizes, int n_in,
                              void* d_out, int out_size) {
  Prm p;
  p.xc    = (const int*)  d_in[0];
  p.xcat  = (const int*)  d_in[1];
  p.sos   = (const float*)d_in[2];
  p.emb   = (const float*)d_in[3];
  p.hw    = (const float*)d_in[4];
  p.hb    = (const float*)d_in[5];
  p.ewqkv = (const float*)d_in[6];
  p.ebqkv = (const float*)d_in[7];
  p.ewo   = (const float*)d_in[8];
  p.ebo   = (const float*)d_in[9];
  p.ew1   = (const float*)d_in[10];
  p.eb1   = (const float*)d_in[11];
  p.ew2   = (const float*)d_in[12];
  p.eb2   = (const float*)d_in[13];
  p.elnw  = (const float*)d_in[14];
  p.elnb  = (const float*)d_in[15];
  p.swqkv = (const float*)d_in[16];
  p.sbqkv = (const float*)d_in[17];
  p.swo   = (const float*)d_in[18];
  p.sbo   = (const float*)d_in[19];
  p.cwqkv = (const float*)d_in[20];
  p.cbqkv = (const float*)d_in[21];
  p.cwo   = (const float*)d_in[22];
  p.cbo   = (const float*)d_in[23];
  p.dw1   = (const float*)d_in[24];
  p.db1   = (const float*)d_in[25];
  p.dw2   = (const float*)d_in[26];
  p.db2   = (const float*)d_in[27];
  p.dlnw  = (const float*)d_in[28];
  p.dlnb  = (const float*)d_in[29];
  p.lnfw  = (const float*)d_in[30];
  p.lnfb  = (const float*)d_in[31];
  p.out   = (float*)d_out;
  mega<<<NB, NT>>>(p);
}

// round 16
// speedup vs baseline: 1.0723x; 1.0723x over previous
#include <cuda_runtime.h>
#include <math.h>
#include <stdint.h>

#define NLY 6
#define DM 256
#define FFD 1024
#define VC 1024
#define SL 48
#define BSZ 64
#define NH 8
#define DHD 32
#define LT 49
#define ROWS_E (BSZ*SL)
#define NB 148
#define NT 512

// ---------------- device scratch ----------------
__device__ __align__(16) float g_pe[LT*DM];
__device__ unsigned g_keys[2*SL];
__device__ __align__(16) float g_X[ROWS_E*DM];
__device__ __align__(16) float g_T1[ROWS_E*FFD];
__device__ __align__(16) float g_T2[ROWS_E*DM];
__device__ __align__(16) float g_T3[ROWS_E*DM];
__device__ __align__(16) float g_mem[ROWS_E*DM];
__device__ __align__(16) float g_cK[NLY*ROWS_E*DM];
__device__ __align__(16) float g_cV[NLY*ROWS_E*DM];
__device__ __align__(16) float g_sK[NLY*BSZ*LT*DM];
__device__ __align__(16) float g_sV[NLY*BSZ*LT*DM];
__device__ unsigned g_barcnt = 0;
__device__ unsigned g_bargen = 0;

struct Prm {
  const int *xc, *xcat;
  const float *sos, *emb, *hw, *hb;
  const float *ewqkv, *ebqkv, *ewo, *ebo, *ew1, *eb1, *ew2, *eb2, *elnw, *elnb;
  const float *swqkv, *sbqkv, *swo, *sbo;
  const float *cwqkv, *cbqkv, *cwo, *cbo;
  const float *dw1, *db1, *dw2, *db2, *dlnw, *dlnb, *lnfw, *lnfb;
  float* out;
};

// ---------------- grid barrier (encoder phases only) ----------------
__device__ __forceinline__ void gridbar() {
  __threadfence();
  __syncthreads();
  if (threadIdx.x == 0) {
    unsigned gen = *(volatile unsigned*)&g_bargen;
    if (atomicAdd(&g_barcnt, 1u) == NB - 1u) {
      g_barcnt = 0u;
      __threadfence();
      atomicAdd(&g_bargen, 1u);
    } else {
      while (*(volatile unsigned*)&g_bargen == gen) __nanosleep(64);
    }
  }
  __syncthreads();
  __threadfence();   // gpu-scope => invalidate stale L1 lines
}

// ---------------- Threefry-2x32, 20 rounds ----------------
__device__ __forceinline__ uint2 tf2x32(unsigned k0, unsigned k1,
                                        unsigned x0, unsigned x1) {
  unsigned ks2 = k0 ^ k1 ^ 0x1BD11BDAu;
  x0 += k0; x1 += k1;
#define TFR(r) { x0 += x1; x1 = (x1 << (r)) | (x1 >> (32 - (r))); x1 ^= x0; }
  TFR(13) TFR(15) TFR(26) TFR(6)   x0 += k1;  x1 += ks2 + 1u;
  TFR(17) TFR(29) TFR(16) TFR(24)  x0 += ks2; x1 += k0 + 2u;
  TFR(13) TFR(15) TFR(26) TFR(6)   x0 += k0;  x1 += k1 + 3u;
  TFR(17) TFR(29) TFR(16) TFR(24)  x0 += k1;  x1 += ks2 + 4u;
  TFR(13) TFR(15) TFR(26) TFR(6)   x0 += ks2; x1 += k0 + 5u;
#undef TFR
  return make_uint2(x0, x1);
}

__device__ __forceinline__ float pef(int l, int d) {
  const float c = (float)(-9.210340371976184 / 256.0);
  float dv = expf((float)(2 * (d >> 1)) * c);
  float ang = (float)l * dv;
  return (d & 1) ? cosf(ang) : sinf(ang);
}

// MLP-8 dot: n4 float4 elements, 8 concurrent weight streams
__device__ __forceinline__ float dot8(const float* xs, const float* w_, int n4) {
  float acc[8] = {};
  const float4* x4 = (const float4*)xs;
  const float4* w4 = (const float4*)w_;
  for (int i = 0; i < n4; i += 8) {
    float4 wv[8], xv[8];
#pragma unroll
    for (int j = 0; j < 8; j++) wv[j] = __ldg(w4 + i + j);
#pragma unroll
    for (int j = 0; j < 8; j++) xv[j] = x4[i + j];
#pragma unroll
    for (int j = 0; j < 8; j++) {
      acc[j] = fmaf(xv[j].x, wv[j].x, acc[j]);
      acc[j] = fmaf(xv[j].y, wv[j].y, acc[j]);
      acc[j] = fmaf(xv[j].z, wv[j].z, acc[j]);
      acc[j] = fmaf(xv[j].w, wv[j].w, acc[j]);
    }
  }
  return ((acc[0] + acc[1]) + (acc[2] + acc[3])) +
         ((acc[4] + acc[5]) + (acc[6] + acc[7]));
}

// 32-float dot (smem q x global k-row)
__device__ __forceinline__ float dot32(const float* q, const float* k) {
  float s = 0.f;
  const float4* a = (const float4*)q;
  const float4* b = (const float4*)k;
#pragma unroll
  for (int i = 0; i < 8; i++) {
    float4 x = a[i], y = __ldg(b + i);
    s = fmaf(x.x,y.x,fmaf(x.y,y.y,fmaf(x.z,y.z,fmaf(x.w,y.w,s))));
  }
  return s;
}

// full-block sum over 512 threads
__device__ __forceinline__ float blksumall(float v, float* red) {
  int lane = threadIdx.x & 31, wp = threadIdx.x >> 5;
#pragma unroll
  for (int o = 16; o; o >>= 1) v += __shfl_xor_sync(0xffffffffu, v, o);
  if (!lane) red[wp] = v;
  __syncthreads();
  float t = 0.f;
#pragma unroll
  for (int i = 0; i < 16; i++) t += red[i];
  __syncthreads();
  return t;
}

// LN over a 256-value row held by threads 0-255 (others contribute 0)
__device__ __forceinline__ float ln256(float val, int active, const float* w,
                                       const float* b, float* red, int n) {
  float mean = blksumall(active ? val : 0.f, red) * (1.f / 256.f);
  float dd = val - mean;
  float var = blksumall(active ? dd * dd : 0.f, red) * (1.f / 256.f);
  return dd * rsqrtf(var + 1e-5f) * __ldg(w + n) + __ldg(b + n);
}

// 64x64 tile of C = A(M,K)@B(N,K)^T + bias (+resid)(+relu); 512 threads
__device__ __noinline__ void gtile(const float* A, const float* B,
                                   const float* bias, const float* resid,
                                   float* C, int N, int K, int relu,
                                   int bx, int by, float* SM) {
  float* As = SM;              // [32][68]
  float* Bs = SM + 32 * 68;    // [32][68]
  int t = threadIdx.x, tx = t & 15, ty = t >> 4;
  float acc[2][4] = {};
  const float* Ab = A + (size_t)(by * 64) * K;
  const float* Bb = B + (size_t)(bx * 64) * K;
  int lrow = t >> 3, lcol = (t & 7) * 4;
  for (int k0 = 0; k0 < K; k0 += 32) {
    float4 va = *(const float4*)(Ab + (size_t)lrow * K + k0 + lcol);
    As[(lcol + 0) * 68 + lrow] = va.x; As[(lcol + 1) * 68 + lrow] = va.y;
    As[(lcol + 2) * 68 + lrow] = va.z; As[(lcol + 3) * 68 + lrow] = va.w;
    float4 vb = *(const float4*)(Bb + (size_t)lrow * K + k0 + lcol);
    Bs[(lcol + 0) * 68 + lrow] = vb.x; Bs[(lcol + 1) * 68 + lrow] = vb.y;
    Bs[(lcol + 2) * 68 + lrow] = vb.z; Bs[(lcol + 3) * 68 + lrow] = vb.w;
    __syncthreads();
#pragma unroll
    for (int kk = 0; kk < 32; kk++) {
      float a[2], bb[4];
#pragma unroll
      for (int i = 0; i < 2; i++) a[i] = As[kk * 68 + ty * 2 + i];
#pragma unroll
      for (int j = 0; j < 4; j++) bb[j] = Bs[kk * 68 + tx * 4 + j];
#pragma unroll
      for (int i = 0; i < 2; i++)
#pragma unroll
        for (int j = 0; j < 4; j++) acc[i][j] = fmaf(a[i], bb[j], acc[i][j]);
    }
    __syncthreads();
  }
#pragma unroll
  for (int i = 0; i < 2; i++) {
    int m = by * 64 + ty * 2 + i;
#pragma unroll
    for (int j = 0; j < 4; j++) {
      int n = bx * 64 + tx * 4 + j;
      float v = acc[i][j];
      if (bias)  v += __ldg(bias + n);
      if (resid) v += resid[(size_t)m * N + n];
      if (relu)  v = fmaxf(v, 0.f);
      C[(size_t)m * N + n] = v;
    }
  }
  __syncthreads();
}

// encoder self-attn for one (head, batch); 512 threads / 16 warps
__device__ __noinline__ void enc_attn_unit(const float* QKV, float* O,
                                           int h, int b, float* SM) {
  float* Qs = SM;
  float* Ks = SM + 1536;
  float* Vs = SM + 3072;
  float* pr = SM + 4608;     // [16][48]
  int t = threadIdx.x;
  for (int e = t; e < SL * DHD; e += NT) {
    int j = e >> 5, d = e & 31;
    const float* base = QKV + (size_t)(b * SL + j) * 768 + h * DHD + d;
    Qs[e] = base[0]; Ks[e] = base[256]; Vs[e] = base[512];
  }
  __syncthreads();
  int w = t >> 5, lane = t & 31;
  const float scale = 0.17677669529663687f;
  for (int q = w; q < SL; q += 16) {
    float s0 = 0.f, s1 = -1e30f;
#pragma unroll
    for (int d = 0; d < DHD; d++) s0 += Qs[q * 32 + d] * Ks[lane * 32 + d];
    s0 *= scale;
    if (lane < SL - 32) {
      float a = 0.f;
#pragma unroll
      for (int d = 0; d < DHD; d++) a += Qs[q * 32 + d] * Ks[(lane + 32) * 32 + d];
      s1 = a * scale;
    }
    float mx = fmaxf(s0, s1);
#pragma unroll
    for (int o = 16; o; o >>= 1) mx = fmaxf(mx, __shfl_xor_sync(~0u, mx, o));
    float e0 = expf(s0 - mx);
    float e1 = (lane < SL - 32) ? expf(s1 - mx) : 0.f;
    float sum = e0 + e1;
#pragma unroll
    for (int o = 16; o; o >>= 1) sum += __shfl_xor_sync(~0u, sum, o);
    float inv = 1.f / sum;
    pr[w * SL + lane] = e0 * inv;
    if (lane < SL - 32) pr[w * SL + lane + 32] = e1 * inv;
    __syncwarp();
    float acc = 0.f;
#pragma unroll 8
    for (int j = 0; j < SL; j++) acc += pr[w * SL + j] * Vs[j * 32 + lane];
    O[(size_t)(b * SL + q) * DM + h * DHD + lane] = acc;
    __syncwarp();
  }
  __syncthreads();
}

__device__ __forceinline__ void ln_rows(const float* x, const float* w,
                                        const float* b, float* out, int M,
                                        float* red) {
  int t = threadIdx.x;
  for (int r = blockIdx.x; r < M; r += NB) {
    float v = (t < 256) ? x[(size_t)r * DM + t] : 0.f;
    float mean = blksumall(v, red) * (1.f / 256.f);
    float dd = v - mean;
    float var = blksumall((t < 256) ? dd * dd : 0.f, red) * (1.f / 256.f);
    if (t < 256)
      out[(size_t)r * DM + t] = dd * rsqrtf(var + 1e-5f) * w[t] + b[t];
  }
}

// ---------------- the megakernel ----------------
__global__ __launch_bounds__(NT, 1) void mega(Prm p) {
  __shared__ __align__(16) float SM[6144];
  const int bid = blockIdx.x, tid = threadIdx.x;
  const int gtid = bid * NT + tid;
  const int GT = NB * NT;
  const float scale = 0.17677669529663687f;

  // ---- init: pe, step keys, encoder embed ----
  for (int e = gtid; e < LT * DM; e += GT) g_pe[e] = pef(e >> 8, e & 255);
  if (gtid < SL) {
    uint2 r = tf2x32(0u, 42u, 0u, (unsigned)gtid);
    g_keys[2 * gtid] = r.x; g_keys[2 * gtid + 1] = r.y;
  }
  for (int e = gtid; e < ROWS_E * DM; e += GT) {
    int r = e >> 8, d = e & 255, b = r / SL, s = r % SL;
    int tok = (s < 32) ? p.xc[b * 32 + s] : p.xcat[b * 16 + (s - 32)];
    g_X[e] = p.emb[((size_t)s * VC + tok) * DM + d] + pef(s, d);
  }
  gridbar();

  // ---- encoder ----
  for (int l = 0; l < NLY; l++) {
    for (int t = bid; t < 576; t += NB)
      gtile(g_X, p.ewqkv + (size_t)l * 196608, p.ebqkv + l * 768, nullptr,
            g_T1, 768, 256, 0, t % 12, t / 12, SM);
    gridbar();
    for (int u = bid; u < NH * BSZ; u += NB)
      enc_attn_unit(g_T1, g_T2, u & 7, u >> 3, SM);
    gridbar();
    for (int t = bid; t < 192; t += NB)
      gtile(g_T2, p.ewo + (size_t)l * 65536, p.ebo + l * 256, g_X,
            g_T3, 256, 256, 0, t % 4, t / 4, SM);
    gridbar();
    ln_rows(g_T3, p.elnw + l * 512, p.elnb + l * 512, g_X, ROWS_E, SM);
    gridbar();
    for (int t = bid; t < 768; t += NB)
      gtile(g_X, p.ew1 + (size_t)l * 262144, p.eb1 + l * 1024, nullptr,
            g_T1, 1024, 256, 1, t % 16, t / 16, SM);
    gridbar();
    for (int t = bid; t < 192; t += NB)
      gtile(g_T1, p.ew2 + (size_t)l * 262144, p.eb2 + l * 256, g_X,
            g_T2, 256, 1024, 0, t % 4, t / 4, SM);
    gridbar();
    ln_rows(g_T2, p.elnw + l * 512 + 256, p.elnb + l * 512 + 256, g_X, ROWS_E, SM);
    gridbar();
  }
  ln_rows(g_X, p.lnfw, p.lnfb, g_mem, ROWS_E, SM);
  gridbar();

  // ---- cross-attn K/V precompute ----
  for (int t = bid; t < 2304; t += NB) {
    int l = t / 384, r = t % 384, kv = r / 192, tile = r % 192;
    const float* B = p.cwqkv + (size_t)l * 196608 + (size_t)(256 + kv * 256) * 256;
    const float* bias = p.cbqkv + l * 768 + 256 + kv * 256;
    float* C = (kv ? g_cV : g_cK) + (size_t)l * ROWS_E * DM;
    gtile(g_mem, B, bias, nullptr, C, 256, 256, 0, tile % 4, tile / 4, SM);
  }
  gridbar();   // last grid barrier

  if (bid >= BSZ) return;   // 64 blocks decode, one row each

  // ---- decode: one batch row per block, 512 threads / 16 warps ----
  const int b = bid;
  float* xb  = SM;                  // 256
  float* qb  = SM + 256;            // 256
  float* ob  = SM + 512;            // 256
  float* pr  = SM + 768;            // 8*49 -> 400
  float* red = SM + 1168;           // 16
  float* hb  = SM + 1280;           // 1024
  float* sc  = SM + 2304;           // 512 (K-split partials)
  float* bv  = SM + 2816;           // 512
  int*   bix = (int*)(SM + 3328);   // 512
  int*   chs = (int*)(SM + 3840);   // 48
  const int w = tid >> 5, lane = tid & 31;
  const int half = tid >> 8;        // K-split half
  const int nn = tid & 255;
  const int act = (tid < 256);

  if (act) xb[nn] = p.sos[nn] + g_pe[nn];
  __syncthreads();

  for (int step = 0; step < SL; step++) {
    for (int l = 0; l < NLY; l++) {
      float* Kc = g_sK + (size_t)(l * BSZ + b) * LT * DM;
      float* Vc = g_sV + (size_t)(l * BSZ + b) * LT * DM;
      // --- A: qkv GEMV (768 outputs, MLP-8 dots) ---
      {
        const float* W = p.swqkv + (size_t)l * 196608;
        const float* bias = p.sbqkv + l * 768;
        {
          float y = dot8(xb, W + (size_t)tid * 256, 64) + __ldg(bias + tid);
          if (tid < 256) qb[tid] = y;
          else           Kc[step * DM + tid - 256] = y;
        }
        if (act) {
          int n = 512 + tid;
          Vc[step * DM + tid] = dot8(xb, W + (size_t)n * 256, 64) + __ldg(bias + n);
        }
        __syncthreads();
      }
      // --- B: self-attention (warps 0-7, one head each) ---
      if (w < 8) {
        const float* Kb = Kc + w * DHD;
        const float* Vb = Vc + w * DHD;
        float s0 = -1e30f, s1 = -1e30f;
        if (lane <= step)      s0 = dot32(qb + w * 32, Kb + lane * DM) * scale;
        if (lane + 32 <= step) s1 = dot32(qb + w * 32, Kb + (lane + 32) * DM) * scale;
        float mx = fmaxf(s0, s1);
#pragma unroll
        for (int o = 16; o; o >>= 1) mx = fmaxf(mx, __shfl_xor_sync(~0u, mx, o));
        float e0 = (lane <= step) ? expf(s0 - mx) : 0.f;
        float e1 = (lane + 32 <= step) ? expf(s1 - mx) : 0.f;
        float sum = e0 + e1;
#pragma unroll
        for (int o = 16; o; o >>= 1) sum += __shfl_xor_sync(~0u, sum, o);
        float inv = 1.f / sum;
        pr[w * LT + lane] = e0 * inv;
        if (lane + 32 < LT) pr[w * LT + lane + 32] = e1 * inv;
        __syncwarp();
        float acc = 0.f;
#pragma unroll 8
        for (int j = 0; j <= step; j++) acc += pr[w * LT + j] * Vb[j * DM + lane];
        ob[w * 32 + lane] = acc;
      }
      __syncthreads();
      // --- C: self out-proj (K-split) + resid + LN ---
      {
        sc[tid] = dot8(ob + half * 128,
                       p.swo + (size_t)l * 65536 + (size_t)nn * 256 + half * 128, 32);
        __syncthreads();
        float val = 0.f;
        if (act)
          val = xb[nn] + __ldg(p.sbo + l * 256 + nn) + sc[nn] + sc[nn + 256];
        float y = ln256(val, act, p.dlnw + l * 768, p.dlnb + l * 768, red, nn);
        if (act) xb[nn] = y;
        __syncthreads();
      }
      // --- D: cross Q GEMV (K-split) ---
      {
        sc[tid] = dot8(xb + half * 128,
                       p.cwqkv + (size_t)l * 196608 + (size_t)nn * 256 + half * 128, 32);
        __syncthreads();
        if (act) qb[nn] = __ldg(p.cbqkv + l * 768 + nn) + sc[nn] + sc[nn + 256];
        __syncthreads();
      }
      // --- E: cross-attention (warps 0-7) ---
      if (w < 8) {
        const float* Kb = g_cK + ((size_t)l * ROWS_E + b * SL) * DM + w * DHD;
        const float* Vb = g_cV + ((size_t)l * ROWS_E + b * SL) * DM + w * DHD;
        float s0 = dot32(qb + w * 32, Kb + lane * DM) * scale;
        float s1 = (lane < SL - 32)
                   ? dot32(qb + w * 32, Kb + (lane + 32) * DM) * scale : -1e30f;
        float mx = fmaxf(s0, s1);
#pragma unroll
        for (int o = 16; o; o >>= 1) mx = fmaxf(mx, __shfl_xor_sync(~0u, mx, o));
        float e0 = expf(s0 - mx);
        float e1 = (lane < SL - 32) ? expf(s1 - mx) : 0.f;
        float sum = e0 + e1;
#pragma unroll
        for (int o = 16; o; o >>= 1) sum += __shfl_xor_sync(~0u, sum, o);
        float inv = 1.f / sum;
        pr[w * SL + lane] = e0 * inv;
        if (lane < SL - 32) pr[w * SL + lane + 32] = e1 * inv;
        __syncwarp();
        float acc = 0.f;
#pragma unroll 8
        for (int j = 0; j < SL; j++) acc += pr[w * SL + j] * Vb[j * DM + lane];
        ob[w * 32 + lane] = acc;
      }
      __syncthreads();
      // --- F: cross out-proj (K-split) + resid + LN ---
      {
        sc[tid] = dot8(ob + half * 128,
                       p.cwo + (size_t)l * 65536 + (size_t)nn * 256 + half * 128, 32);
        __syncthreads();
        float val = 0.f;
        if (act)
          val = xb[nn] + __ldg(p.cbo + l * 256 + nn) + sc[nn] + sc[nn + 256];
        float y = ln256(val, act, p.dlnw + l * 768 + 256, p.dlnb + l * 768 + 256,
                        red, nn);
        if (act) xb[nn] = y;
        __syncthreads();
      }
      // --- G: FF1 (1024 outputs, 2 MLP-8 dots per thread, relu) ---
      {
        const float* W1 = p.dw1 + (size_t)l * 262144;
#pragma unroll
        for (int j = 0; j < 2; j++) {
          int n = tid + j * 512;
          float y = dot8(xb, W1 + (size_t)n * 256, 64) + __ldg(p.db1 + l * 1024 + n);
          hb[n] = fmaxf(y, 0.f);
        }
        __syncthreads();
      }
      // --- H: FF2 (K-split over 1024) + resid + LN ---
      {
        sc[tid] = dot8(hb + half * 512,
                       p.dw2 + (size_t)l * 262144 + (size_t)nn * 1024 + half * 512, 128);
        __syncthreads();
        float val = 0.f;
        if (act)
          val = xb[nn] + __ldg(p.db2 + l * 256 + nn) + sc[nn] + sc[nn + 256];
        float y = ln256(val, act, p.dlnw + l * 768 + 512, p.dlnb + l * 768 + 512,
                        red, nn);
        if (act) xb[nn] = y;
        __syncthreads();
      }
    }
    // --- final LN ---
    {
      float v = act ? xb[nn] : 0.f;
      float y = ln256(v, act, p.lnfw + 256, p.lnfb + 256, red, nn);
      if (act) qb[nn] = y;
      __syncthreads();
    }
    // --- head GEMV + logits out + Gumbel-max sample + next-token embed ---
    {
      const float* HW = p.hw + (size_t)step * VC * DM;
      const float* HB = p.hb + step * VC;
      float* outl = p.out + 3072 + ((size_t)step * BSZ + b) * VC;
#pragma unroll
      for (int j = 0; j < 2; j++) {
        int n = tid + j * 512;
        float y = dot8(qb, HW + (size_t)n * 256, 64) + __ldg(HB + n);
        hb[n] = y; outl[n] = y;
      }
      __syncthreads();
      unsigned k0 = g_keys[2 * step], k1 = g_keys[2 * step + 1];
      const float tiny = 1.17549435e-38f;
      float best = -1e38f; int bi = 0;
#pragma unroll
      for (int j = 0; j < 2; j++) {
        int v = tid + j * 512;
        uint2 r = tf2x32(k0, k1, 0u, (unsigned)(b * VC + v));
        unsigned bits = r.x ^ r.y;
        float f = __uint_as_float((bits >> 9) | 0x3f800000u) - 1.0f;
        float u = fmaxf(tiny, f + tiny);
        float g = -logf(-logf(u));
        float vv = g + __fdiv_rn(hb[v], 0.1f);
        if (vv > best || (vv == best && v < bi)) { best = vv; bi = v; }
      }
      bv[tid] = best; bix[tid] = bi;
      __syncthreads();
      for (int off = 256; off; off >>= 1) {
        if (tid < off) {
          float ov = bv[tid + off]; int oi = bix[tid + off];
          if (ov > bv[tid] || (ov == bv[tid] && oi < bix[tid])) {
            bv[tid] = ov; bix[tid] = oi;
          }
        }
        __syncthreads();
      }
      int ch = bix[0];
      if (tid == 0) chs[step] = ch;
      if (step < SL - 1 && act)
        xb[nn] = __ldg(p.emb + ((size_t)step * VC + ch) * DM + nn) +
                 g_pe[(step + 1) * DM + nn];
      __syncthreads();
    }
  }
  // ---- outputs: s_cont [64,32] then s_cat [64,16] ----
  if (tid < 32)      p.out[b * 32 + tid] = (float)chs[tid];
  else if (tid < 48) p.out[2048 + b * 16 + (tid - 32)] = (float)chs[tid];
}

extern "C" void kernel_launch(void* const* d_in, const int* in_sizes, int n_in,
                              void* d_out, int out_size) {
  Prm p;
  p.xc    = (const int*)  d_in[0];
  p.xcat  = (const int*)  d_in[1];
  p.sos   = (const float*)d_in[2];
  p.emb   = (const float*)d_in[3];
  p.hw    = (const float*)d_in[4];
  p.hb    = (const float*)d_in[5];
  p.ewqkv = (const float*)d_in[6];
  p.ebqkv = (const float*)d_in[7];
  p.ewo   = (const float*)d_in[8];
  p.ebo   = (const float*)d_in[9];
  p.ew1   = (const float*)d_in[10];
  p.eb1   = (const float*)d_in[11];
  p.ew2   = (const float*)d_in[12];
  p.eb2   = (const float*)d_in[13];
  p.elnw  = (const float*)d_in[14];
  p.elnb  = (const float*)d_in[15];
  p.swqkv = (const float*)d_in[16];
  p.sbqkv = (const float*)d_in[17];
  p.swo   = (const float*)d_in[18];
  p.sbo   = (const float*)d_in[19];
  p.cwqkv = (const float*)d_in[20];
  p.cbqkv = (const float*)d_in[21];
  p.cwo   = (const float*)d_in[22];
  p.cbo   = (const float*)d_in[23];
  p.dw1   = (const float*)d_in[24];
  p.db1   = (const float*)d_in[25];
  p.dw2   = (const float*)d_in[26];
  p.db2   = (const float*)d_in[27];
  p.dlnw  = (const float*)d_in[28];
  p.dlnb  = (const float*)d_in[29];
  p.lnfw  = (const float*)d_in[30];
  p.lnfb  = (const float*)d_in[31];
  p.out   = (float*)d_out;
  mega<<<NB, NT>>>(p);
}

// round 17
// speedup vs baseline: 2.3958x; 2.2343x over previous
#include <cuda_runtime.h>
#include <math.h>
#include <stdint.h>

#define NLY 6
#define DM 256
#define FFD 1024
#define VC 1024
#define SL 48
#define BSZ 64
#define NH 8
#define DHD 32
#define LT 49
#define ROWS_E (BSZ*SL)
#define NB 148
#define NT 512

// ---------------- device scratch ----------------
__device__ __align__(16) float g_pe[LT*DM];
__device__ unsigned g_keys[2*SL];
__device__ __align__(16) float g_X[ROWS_E*DM];
__device__ __align__(16) float g_T1[ROWS_E*FFD];
__device__ __align__(16) float g_T2[ROWS_E*DM];
__device__ __align__(16) float g_T3[ROWS_E*DM];
__device__ __align__(16) float g_mem[ROWS_E*DM];
__device__ __align__(16) float g_cK[NLY*ROWS_E*DM];
__device__ __align__(16) float g_cV[NLY*ROWS_E*DM];
__device__ __align__(16) float g_sK[NLY*BSZ*LT*DM];
__device__ __align__(16) float g_sV[NLY*BSZ*LT*DM];
__device__ unsigned g_barcnt = 0;
__device__ unsigned g_bargen = 0;

struct Prm {
  const int *xc, *xcat;
  const float *sos, *emb, *hw, *hb;
  const float *ewqkv, *ebqkv, *ewo, *ebo, *ew1, *eb1, *ew2, *eb2, *elnw, *elnb;
  const float *swqkv, *sbqkv, *swo, *sbo;
  const float *cwqkv, *cbqkv, *cwo, *cbo;
  const float *dw1, *db1, *dw2, *db2, *dlnw, *dlnb, *lnfw, *lnfb;
  float* out;
};

// ---------------- grid barrier (encoder phases only) ----------------
__device__ __forceinline__ void gridbar() {
  __threadfence();
  __syncthreads();
  if (threadIdx.x == 0) {
    unsigned gen = *(volatile unsigned*)&g_bargen;
    if (atomicAdd(&g_barcnt, 1u) == NB - 1u) {
      g_barcnt = 0u;
      __threadfence();
      atomicAdd(&g_bargen, 1u);
    } else {
      while (*(volatile unsigned*)&g_bargen == gen) __nanosleep(64);
    }
  }
  __syncthreads();
  __threadfence();   // gpu-scope => invalidate stale L1 lines
}

// ---------------- Threefry-2x32, 20 rounds ----------------
__device__ __forceinline__ uint2 tf2x32(unsigned k0, unsigned k1,
                                        unsigned x0, unsigned x1) {
  unsigned ks2 = k0 ^ k1 ^ 0x1BD11BDAu;
  x0 += k0; x1 += k1;
#define TFR(r) { x0 += x1; x1 = (x1 << (r)) | (x1 >> (32 - (r))); x1 ^= x0; }
  TFR(13) TFR(15) TFR(26) TFR(6)   x0 += k1;  x1 += ks2 + 1u;
  TFR(17) TFR(29) TFR(16) TFR(24)  x0 += ks2; x1 += k0 + 2u;
  TFR(13) TFR(15) TFR(26) TFR(6)   x0 += k0;  x1 += k1 + 3u;
  TFR(17) TFR(29) TFR(16) TFR(24)  x0 += k1;  x1 += ks2 + 4u;
  TFR(13) TFR(15) TFR(26) TFR(6)   x0 += ks2; x1 += k0 + 5u;
#undef TFR
  return make_uint2(x0, x1);
}

__device__ __forceinline__ float pef(int l, int d) {
  const float c = (float)(-9.210340371976184 / 256.0);
  float dv = expf((float)(2 * (d >> 1)) * c);
  float ang = (float)l * dv;
  return (d & 1) ? cosf(ang) : sinf(ang);
}

__device__ __forceinline__ float vdot4(float4 a, float4 b, float s) {
  return fmaf(a.x, b.x, fmaf(a.y, b.y, fmaf(a.z, b.z, fmaf(a.w, b.w, s))));
}

// warp-coalesced dual-row dot, K=256: lanes split K; butterfly reduce.
__device__ __forceinline__ void wdot256x2(const float* xs, const float* w0_,
                                          const float* w1_, int lane,
                                          float& o0, float& o1) {
  const float4* x4 = (const float4*)xs;
  const float4* w0 = (const float4*)w0_;
  const float4* w1 = (const float4*)w1_;
  float4 p0 = __ldg(w0 + lane), p1 = __ldg(w0 + lane + 32);
  float4 q0 = __ldg(w1 + lane), q1 = __ldg(w1 + lane + 32);
  float4 xa = x4[lane], xc = x4[lane + 32];
  float s0 = vdot4(xc, p1, vdot4(xa, p0, 0.f));
  float s1 = vdot4(xc, q1, vdot4(xa, q0, 0.f));
#pragma unroll
  for (int o = 16; o; o >>= 1) {
    s0 += __shfl_xor_sync(0xffffffffu, s0, o);
    s1 += __shfl_xor_sync(0xffffffffu, s1, o);
  }
  o0 = s0; o1 = s1;
}

// warp-coalesced dual-row dot, K=1024
__device__ __forceinline__ void wdot1024x2(const float* xs, const float* w0_,
                                           const float* w1_, int lane,
                                           float& o0, float& o1) {
  const float4* x4 = (const float4*)xs;
  const float4* w0 = (const float4*)w0_;
  const float4* w1 = (const float4*)w1_;
  float s0 = 0.f, s1 = 0.f;
#pragma unroll
  for (int j = 0; j < 8; j++) {
    float4 xa = x4[lane + 32 * j];
    s0 = vdot4(xa, __ldg(w0 + lane + 32 * j), s0);
    s1 = vdot4(xa, __ldg(w1 + lane + 32 * j), s1);
  }
#pragma unroll
  for (int o = 16; o; o >>= 1) {
    s0 += __shfl_xor_sync(0xffffffffu, s0, o);
    s1 += __shfl_xor_sync(0xffffffffu, s1, o);
  }
  o0 = s0; o1 = s1;
}

// 32-float dot (smem q x global k-row)
__device__ __forceinline__ float dot32(const float* q, const float* k) {
  float s = 0.f;
  const float4* a = (const float4*)q;
  const float4* b = (const float4*)k;
#pragma unroll
  for (int i = 0; i < 8; i++) {
    float4 x = a[i], y = __ldg(b + i);
    s = fmaf(x.x,y.x,fmaf(x.y,y.y,fmaf(x.z,y.z,fmaf(x.w,y.w,s))));
  }
  return s;
}

// full-block sum over 512 threads
__device__ __forceinline__ float blksumall(float v, float* red) {
  int lane = threadIdx.x & 31, wp = threadIdx.x >> 5;
#pragma unroll
  for (int o = 16; o; o >>= 1) v += __shfl_xor_sync(0xffffffffu, v, o);
  if (!lane) red[wp] = v;
  __syncthreads();
  float t = 0.f;
#pragma unroll
  for (int i = 0; i < 16; i++) t += red[i];
  __syncthreads();
  return t;
}

// LN over a 256-value row held by threads 0-255 (others contribute 0)
__device__ __forceinline__ float ln256(float val, int active, const float* w,
                                       const float* b, float* red, int n) {
  float mean = blksumall(active ? val : 0.f, red) * (1.f / 256.f);
  float dd = val - mean;
  float var = blksumall(active ? dd * dd : 0.f, red) * (1.f / 256.f);
  return dd * rsqrtf(var + 1e-5f) * __ldg(w + n) + __ldg(b + n);
}

// 64x64 tile of C = A(M,K)@B(N,K)^T + bias (+resid)(+relu); 512 threads
__device__ __noinline__ void gtile(const float* A, const float* B,
                                   const float* bias, const float* resid,
                                   float* C, int N, int K, int relu,
                                   int bx, int by, float* SM) {
  float* As = SM;              // [32][68]
  float* Bs = SM + 32 * 68;    // [32][68]
  int t = threadIdx.x, tx = t & 15, ty = t >> 4;
  float acc[2][4] = {};
  const float* Ab = A + (size_t)(by * 64) * K;
  const float* Bb = B + (size_t)(bx * 64) * K;
  int lrow = t >> 3, lcol = (t & 7) * 4;
  for (int k0 = 0; k0 < K; k0 += 32) {
    float4 va = *(const float4*)(Ab + (size_t)lrow * K + k0 + lcol);
    As[(lcol + 0) * 68 + lrow] = va.x; As[(lcol + 1) * 68 + lrow] = va.y;
    As[(lcol + 2) * 68 + lrow] = va.z; As[(lcol + 3) * 68 + lrow] = va.w;
    float4 vb = *(const float4*)(Bb + (size_t)lrow * K + k0 + lcol);
    Bs[(lcol + 0) * 68 + lrow] = vb.x; Bs[(lcol + 1) * 68 + lrow] = vb.y;
    Bs[(lcol + 2) * 68 + lrow] = vb.z; Bs[(lcol + 3) * 68 + lrow] = vb.w;
    __syncthreads();
#pragma unroll
    for (int kk = 0; kk < 32; kk++) {
      float a[2], bb[4];
#pragma unroll
      for (int i = 0; i < 2; i++) a[i] = As[kk * 68 + ty * 2 + i];
#pragma unroll
      for (int j = 0; j < 4; j++) bb[j] = Bs[kk * 68 + tx * 4 + j];
#pragma unroll
      for (int i = 0; i < 2; i++)
#pragma unroll
        for (int j = 0; j < 4; j++) acc[i][j] = fmaf(a[i], bb[j], acc[i][j]);
    }
    __syncthreads();
  }
#pragma unroll
  for (int i = 0; i < 2; i++) {
    int m = by * 64 + ty * 2 + i;
#pragma unroll
    for (int j = 0; j < 4; j++) {
      int n = bx * 64 + tx * 4 + j;
      float v = acc[i][j];
      if (bias)  v += __ldg(bias + n);
      if (resid) v += resid[(size_t)m * N + n];
      if (relu)  v = fmaxf(v, 0.f);
      C[(size_t)m * N + n] = v;
    }
  }
  __syncthreads();
}

// encoder self-attn for one (head, batch); 512 threads / 16 warps
__device__ __noinline__ void enc_attn_unit(const float* QKV, float* O,
                                           int h, int b, float* SM) {
  float* Qs = SM;
  float* Ks = SM + 1536;
  float* Vs = SM + 3072;
  float* pr = SM + 4608;     // [16][48]
  int t = threadIdx.x;
  for (int e = t; e < SL * DHD; e += NT) {
    int j = e >> 5, d = e & 31;
    const float* base = QKV + (size_t)(b * SL + j) * 768 + h * DHD + d;
    Qs[e] = base[0]; Ks[e] = base[256]; Vs[e] = base[512];
  }
  __syncthreads();
  int w = t >> 5, lane = t & 31;
  const float scale = 0.17677669529663687f;
  for (int q = w; q < SL; q += 16) {
    float s0 = 0.f, s1 = -1e30f;
#pragma unroll
    for (int d = 0; d < DHD; d++) s0 += Qs[q * 32 + d] * Ks[lane * 32 + d];
    s0 *= scale;
    if (lane < SL - 32) {
      float a = 0.f;
#pragma unroll
      for (int d = 0; d < DHD; d++) a += Qs[q * 32 + d] * Ks[(lane + 32) * 32 + d];
      s1 = a * scale;
    }
    float mx = fmaxf(s0, s1);
#pragma unroll
    for (int o = 16; o; o >>= 1) mx = fmaxf(mx, __shfl_xor_sync(~0u, mx, o));
    float e0 = expf(s0 - mx);
    float e1 = (lane < SL - 32) ? expf(s1 - mx) : 0.f;
    float sum = e0 + e1;
#pragma unroll
    for (int o = 16; o; o >>= 1) sum += __shfl_xor_sync(~0u, sum, o);
    float inv = 1.f / sum;
    pr[w * SL + lane] = e0 * inv;
    if (lane < SL - 32) pr[w * SL + lane + 32] = e1 * inv;
    __syncwarp();
    float acc = 0.f;
#pragma unroll 8
    for (int j = 0; j < SL; j++) acc += pr[w * SL + j] * Vs[j * 32 + lane];
    O[(size_t)(b * SL + q) * DM + h * DHD + lane] = acc;
    __syncwarp();
  }
  __syncthreads();
}

__device__ __forceinline__ void ln_rows(const float* x, const float* w,
                                        const float* b, float* out, int M,
                                        float* red) {
  int t = threadIdx.x;
  for (int r = blockIdx.x; r < M; r += NB) {
    float v = (t < 256) ? x[(size_t)r * DM + t] : 0.f;
    float mean = blksumall(v, red) * (1.f / 256.f);
    float dd = v - mean;
    float var = blksumall((t < 256) ? dd * dd : 0.f, red) * (1.f / 256.f);
    if (t < 256)
      out[(size_t)r * DM + t] = dd * rsqrtf(var + 1e-5f) * w[t] + b[t];
  }
}

// ---------------- the megakernel ----------------
__global__ __launch_bounds__(NT, 1) void mega(Prm p) {
  __shared__ __align__(16) float SM[6144];
  const int bid = blockIdx.x, tid = threadIdx.x;
  const int gtid = bid * NT + tid;
  const int GT = NB * NT;
  const float scale = 0.17677669529663687f;

  // ---- init: pe, step keys, encoder embed ----
  for (int e = gtid; e < LT * DM; e += GT) g_pe[e] = pef(e >> 8, e & 255);
  if (gtid < SL) {
    uint2 r = tf2x32(0u, 42u, 0u, (unsigned)gtid);
    g_keys[2 * gtid] = r.x; g_keys[2 * gtid + 1] = r.y;
  }
  for (int e = gtid; e < ROWS_E * DM; e += GT) {
    int r = e >> 8, d = e & 255, b = r / SL, s = r % SL;
    int tok = (s < 32) ? p.xc[b * 32 + s] : p.xcat[b * 16 + (s - 32)];
    g_X[e] = p.emb[((size_t)s * VC + tok) * DM + d] + pef(s, d);
  }
  gridbar();

  // ---- encoder ----
  for (int l = 0; l < NLY; l++) {
    for (int t = bid; t < 576; t += NB)
      gtile(g_X, p.ewqkv + (size_t)l * 196608, p.ebqkv + l * 768, nullptr,
            g_T1, 768, 256, 0, t % 12, t / 12, SM);
    gridbar();
    for (int u = bid; u < NH * BSZ; u += NB)
      enc_attn_unit(g_T1, g_T2, u & 7, u >> 3, SM);
    gridbar();
    for (int t = bid; t < 192; t += NB)
      gtile(g_T2, p.ewo + (size_t)l * 65536, p.ebo + l * 256, g_X,
            g_T3, 256, 256, 0, t % 4, t / 4, SM);
    gridbar();
    ln_rows(g_T3, p.elnw + l * 512, p.elnb + l * 512, g_X, ROWS_E, SM);
    gridbar();
    for (int t = bid; t < 768; t += NB)
      gtile(g_X, p.ew1 + (size_t)l * 262144, p.eb1 + l * 1024, nullptr,
            g_T1, 1024, 256, 1, t % 16, t / 16, SM);
    gridbar();
    for (int t = bid; t < 192; t += NB)
      gtile(g_T1, p.ew2 + (size_t)l * 262144, p.eb2 + l * 256, g_X,
            g_T2, 256, 1024, 0, t % 4, t / 4, SM);
    gridbar();
    ln_rows(g_T2, p.elnw + l * 512 + 256, p.elnb + l * 512 + 256, g_X, ROWS_E, SM);
    gridbar();
  }
  ln_rows(g_X, p.lnfw, p.lnfb, g_mem, ROWS_E, SM);
  gridbar();

  // ---- cross-attn K/V precompute ----
  for (int t = bid; t < 2304; t += NB) {
    int l = t / 384, r = t % 384, kv = r / 192, tile = r % 192;
    const float* B = p.cwqkv + (size_t)l * 196608 + (size_t)(256 + kv * 256) * 256;
    const float* bias = p.cbqkv + l * 768 + 256 + kv * 256;
    float* C = (kv ? g_cV : g_cK) + (size_t)l * ROWS_E * DM;
    gtile(g_mem, B, bias, nullptr, C, 256, 256, 0, tile % 4, tile / 4, SM);
  }
  gridbar();   // last grid barrier

  if (bid >= BSZ) return;   // 64 blocks decode, one row each

  // ---- decode: one batch row per block, warp-per-row coalesced GEMVs ----
  const int b = bid;
  float* xb  = SM;                  // 256
  float* qb  = SM + 256;            // 256
  float* ob  = SM + 512;            // 256
  float* pr  = SM + 768;            // 8*49 -> 400
  float* red = SM + 1168;           // 16
  float* hb  = SM + 1280;           // 1024 (qkv staging / ff hidden / logits)
  float* sc  = SM + 2304;           // 256 (GEMV outputs pre-LN)
  float* bv  = SM + 2816;           // 512
  int*   bix = (int*)(SM + 3328);   // 512
  int*   chs = (int*)(SM + 3840);   // 48
  const int w = tid >> 5, lane = tid & 31;
  const int nn = tid & 255;
  const int act = (tid < 256);

  if (act) xb[nn] = p.sos[nn] + g_pe[nn];
  __syncthreads();

  for (int step = 0; step < SL; step++) {
    for (int l = 0; l < NLY; l++) {
      float* Kc = g_sK + (size_t)(l * BSZ + b) * LT * DM;
      float* Vc = g_sV + (size_t)(l * BSZ + b) * LT * DM;
      // --- A: qkv GEMV (768 rows), staged in hb; q stays in hb[0..255] ---
      {
        const float* W = p.swqkv + (size_t)l * 196608;
        const float* bias = p.sbqkv + l * 768;
#pragma unroll 2
        for (int g = 0; g < 48; g += 2) {
          int r = w * 48 + g;
          float y0, y1;
          wdot256x2(xb, W + (size_t)r * 256, W + (size_t)(r + 1) * 256,
                    lane, y0, y1);
          if (lane == 0) {
            hb[r]     = y0 + __ldg(bias + r);
            hb[r + 1] = y1 + __ldg(bias + r + 1);
          }
        }
        __syncthreads();
        if (act) {
          Kc[step * DM + nn] = hb[256 + nn];
          Vc[step * DM + nn] = hb[512 + nn];
        }
        __syncthreads();
      }
      // --- B: self-attention (warps 0-7, one head each; q = hb) ---
      if (w < 8) {
        const float* Kb = Kc + w * DHD;
        const float* Vb = Vc + w * DHD;
        float s0 = -1e30f, s1 = -1e30f;
        if (lane <= step)      s0 = dot32(hb + w * 32, Kb + lane * DM) * scale;
        if (lane + 32 <= step) s1 = dot32(hb + w * 32, Kb + (lane + 32) * DM) * scale;
        float mx = fmaxf(s0, s1);
#pragma unroll
        for (int o = 16; o; o >>= 1) mx = fmaxf(mx, __shfl_xor_sync(~0u, mx, o));
        float e0 = (lane <= step) ? expf(s0 - mx) : 0.f;
        float e1 = (lane + 32 <= step) ? expf(s1 - mx) : 0.f;
        float sum = e0 + e1;
#pragma unroll
        for (int o = 16; o; o >>= 1) sum += __shfl_xor_sync(~0u, sum, o);
        float inv = 1.f / sum;
        pr[w * LT + lane] = e0 * inv;
        if (lane + 32 < LT) pr[w * LT + lane + 32] = e1 * inv;
        __syncwarp();
        float acc = 0.f;
#pragma unroll 8
        for (int j = 0; j <= step; j++) acc += pr[w * LT + j] * Vb[j * DM + lane];
        ob[w * 32 + lane] = acc;
      }
      __syncthreads();
      // --- C: self out-proj (256 rows) + resid + LN ---
      {
        const float* W = p.swo + (size_t)l * 65536;
#pragma unroll 2
        for (int g = 0; g < 16; g += 2) {
          int r = w * 16 + g;
          float y0, y1;
          wdot256x2(ob, W + (size_t)r * 256, W + (size_t)(r + 1) * 256,
                    lane, y0, y1);
          if (lane == 0) { sc[r] = y0; sc[r + 1] = y1; }
        }
        __syncthreads();
        float val = 0.f;
        if (act) val = xb[nn] + __ldg(p.sbo + l * 256 + nn) + sc[nn];
        float y = ln256(val, act, p.dlnw + l * 768, p.dlnb + l * 768, red, nn);
        if (act) xb[nn] = y;
        __syncthreads();
      }
      // --- D: cross Q GEMV (256 rows) ---
      {
        const float* W = p.cwqkv + (size_t)l * 196608;
        const float* bias = p.cbqkv + l * 768;
#pragma unroll 2
        for (int g = 0; g < 16; g += 2) {
          int r = w * 16 + g;
          float y0, y1;
          wdot256x2(xb, W + (size_t)r * 256, W + (size_t)(r + 1) * 256,
                    lane, y0, y1);
          if (lane == 0) {
            qb[r]     = y0 + __ldg(bias + r);
            qb[r + 1] = y1 + __ldg(bias + r + 1);
          }
        }
        __syncthreads();
      }
      // --- E: cross-attention (warps 0-7) ---
      if (w < 8) {
        const float* Kb = g_cK + ((size_t)l * ROWS_E + b * SL) * DM + w * DHD;
        const float* Vb = g_cV + ((size_t)l * ROWS_E + b * SL) * DM + w * DHD;
        float s0 = dot32(qb + w * 32, Kb + lane * DM) * scale;
        float s1 = (lane < SL - 32)
                   ? dot32(qb + w * 32, Kb + (lane + 32) * DM) * scale : -1e30f;
        float mx = fmaxf(s0, s1);
#pragma unroll
        for (int o = 16; o; o >>= 1) mx = fmaxf(mx, __shfl_xor_sync(~0u, mx, o));
        float e0 = expf(s0 - mx);
        float e1 = (lane < SL - 32) ? expf(s1 - mx) : 0.f;
        float sum = e0 + e1;
#pragma unroll
        for (int o = 16; o; o >>= 1) sum += __shfl_xor_sync(~0u, sum, o);
        float inv = 1.f / sum;
        pr[w * SL + lane] = e0 * inv;
        if (lane < SL - 32) pr[w * SL + lane + 32] = e1 * inv;
        __syncwarp();
        float acc = 0.f;
#pragma unroll 8
        for (int j = 0; j < SL; j++) acc += pr[w * SL + j] * Vb[j * DM + lane];
        ob[w * 32 + lane] = acc;
      }
      __syncthreads();
      // --- F: cross out-proj (256 rows) + resid + LN ---
      {
        const float* W = p.cwo + (size_t)l * 65536;
#pragma unroll 2
        for (int g = 0; g < 16; g += 2) {
          int r = w * 16 + g;
          float y0, y1;
          wdot256x2(ob, W + (size_t)r * 256, W + (size_t)(r + 1) * 256,
                    lane, y0, y1);
          if (lane == 0) { sc[r] = y0; sc[r + 1] = y1; }
        }
        __syncthreads();
        float val = 0.f;
        if (act) val = xb[nn] + __ldg(p.cbo + l * 256 + nn) + sc[nn];
        float y = ln256(val, act, p.dlnw + l * 768 + 256, p.dlnb + l * 768 + 256,
                        red, nn);
        if (act) xb[nn] = y;
        __syncthreads();
      }
      // --- G: FF1 (1024 rows, relu) -> hb ---
      {
        const float* W1 = p.dw1 + (size_t)l * 262144;
        const float* b1 = p.db1 + l * 1024;
#pragma unroll 2
        for (int g = 0; g < 64; g += 2) {
          int r = w * 64 + g;
          float y0, y1;
          wdot256x2(xb, W1 + (size_t)r * 256, W1 + (size_t)(r + 1) * 256,
                    lane, y0, y1);
          if (lane == 0) {
            hb[r]     = fmaxf(y0 + __ldg(b1 + r), 0.f);
            hb[r + 1] = fmaxf(y1 + __ldg(b1 + r + 1), 0.f);
          }
        }
        __syncthreads();
      }
      // --- H: FF2 (256 rows, K=1024) + resid + LN ---
      {
        const float* W2 = p.dw2 + (size_t)l * 262144;
#pragma unroll 2
        for (int g = 0; g < 16; g += 2) {
          int r = w * 16 + g;
          float y0, y1;
          wdot1024x2(hb, W2 + (size_t)r * 1024, W2 + (size_t)(r + 1) * 1024,
                     lane, y0, y1);
          if (lane == 0) { sc[r] = y0; sc[r + 1] = y1; }
        }
        __syncthreads();
        float val = 0.f;
        if (act) val = xb[nn] + __ldg(p.db2 + l * 256 + nn) + sc[nn];
        float y = ln256(val, act, p.dlnw + l * 768 + 512, p.dlnb + l * 768 + 512,
                        red, nn);
        if (act) xb[nn] = y;
        __syncthreads();
      }
    }
    // --- final LN ---
    {
      float v = act ? xb[nn] : 0.f;
      float y = ln256(v, act, p.lnfw + 256, p.lnfb + 256, red, nn);
      if (act) qb[nn] = y;
      __syncthreads();
    }
    // --- head GEMV (1024 rows) + logits out + Gumbel-max sample ---
    {
      const float* HW = p.hw + (size_t)step * VC * DM;
      const float* HB = p.hb + step * VC;
#pragma unroll 2
      for (int g = 0; g < 64; g += 2) {
        int r = w * 64 + g;
        float y0, y1;
        wdot256x2(qb, HW + (size_t)r * 256, HW + (size_t)(r + 1) * 256,
                  lane, y0, y1);
        if (lane == 0) {
          hb[r]     = y0 + __ldg(HB + r);
          hb[r + 1] = y1 + __ldg(HB + r + 1);
        }
      }
      __syncthreads();
      float* outl = p.out + 3072 + ((size_t)step * BSZ + b) * VC;
      outl[tid] = hb[tid];
      outl[tid + 512] = hb[tid + 512];
      unsigned k0 = g_keys[2 * step], k1 = g_keys[2 * step + 1];
      const float tiny = 1.17549435e-38f;
      float best = -1e38f; int bi = 0;
#pragma unroll
      for (int j = 0; j < 2; j++) {
        int v = tid + j * 512;
        uint2 r = tf2x32(k0, k1, 0u, (unsigned)(b * VC + v));
        unsigned bits = r.x ^ r.y;
        float f = __uint_as_float((bits >> 9) | 0x3f800000u) - 1.0f;
        float u = fmaxf(tiny, f + tiny);
        float g = -logf(-logf(u));
        float vv = g + __fdiv_rn(hb[v], 0.1f);
        if (vv > best || (vv == best && v < bi)) { best = vv; bi = v; }
      }
      bv[tid] = best; bix[tid] = bi;
      __syncthreads();
      for (int off = 256; off; off >>= 1) {
        if (tid < off) {
          float ov = bv[tid + off]; int oi = bix[tid + off];
          if (ov > bv[tid] || (ov == bv[tid] && oi < bix[tid])) {
            bv[tid] = ov; bix[tid] = oi;
          }
        }
        __syncthreads();
      }
      int ch = bix[0];
      if (tid == 0) chs[step] = ch;
      if (step < SL - 1 && act)
        xb[nn] = __ldg(p.emb + ((size_t)step * VC + ch) * DM + nn) +
                 g_pe[(step + 1) * DM + nn];
      __syncthreads();
    }
  }
  // ---- outputs: s_cont [64,32] then s_cat [64,16] ----
  if (tid < 32)      p.out[b * 32 + tid] = (float)chs[tid];
  else if (tid < 48) p.out[2048 + b * 16 + (tid - 32)] = (float)chs[tid];
}

extern "C" void kernel_launch(void* const* d_in, const int* in_sizes, int n_in,
                              void* d_out, int out_size) {
  Prm p;
  p.xc    = (const int*)  d_in[0];
  p.xcat  = (const int*)  d_in[1];
  p.sos   = (const float*)d_in[2];
  p.emb   = (const float*)d_in[3];
  p.hw    = (const float*)d_in[4];
  p.hb    = (const float*)d_in[5];
  p.ewqkv = (const float*)d_in[6];
  p.ebqkv = (const float*)d_in[7];
  p.ewo   = (const float*)d_in[8];
  p.ebo   = (const float*)d_in[9];
  p.ew1   = (const float*)d_in[10];
  p.eb1   = (const float*)d_in[11];
  p.ew2   = (const float*)d_in[12];
  p.eb2   = (const float*)d_in[13];
  p.elnw  = (const float*)d_in[14];
  p.elnb  = (const float*)d_in[15];
  p.swqkv = (const float*)d_in[16];
  p.sbqkv = (const float*)d_in[17];
  p.swo   = (const float*)d_in[18];
  p.sbo   = (const float*)d_in[19];
  p.cwqkv = (const float*)d_in[20];
  p.cbqkv = (const float*)d_in[21];
  p.cwo   = (const float*)d_in[22];
  p.cbo   = (const float*)d_in[23];
  p.dw1   = (const float*)d_in[24];
  p.db1   = (const float*)d_in[25];
  p.dw2   = (const float*)d_in[26];
  p.db2   = (const float*)d_in[27];
  p.dlnw  = (const float*)d_in[28];
  p.dlnb  = (const float*)d_in[29];
  p.lnfw  = (const float*)d_in[30];
  p.lnfb  = (const float*)d_in[31];
  p.out   = (float*)d_out;
  mega<<<NB, NT>>>(p);
}